// round 3
// baseline (speedup 1.0000x reference)
#include <cuda_runtime.h>

// LayerNormSoftmaxChain: x[N,4] -> LN(4) -> @W[4,3] -> softmax(3) -> out[N,3]
// N = 8388608. HBM-streaming: 16B in / 12B out per row (224 MiB total).
//
// R2: fully coalesced global access.
//  - loads:  thread t reads rows blockBase + t + 256*r  -> each LDG.128 warp
//            covers contiguous 512B (4 lines, minimal wavefronts)
//  - stores: results staged in smem (stride-3 float writes, conflict-free),
//            then flushed as contiguous STG.128 across the block
//  - W/gamma/beta in __constant__ (uniform LDC, no L1tex traffic)

__constant__ float cW[12];   // [4,3] row-major
__constant__ float cG[4];
__constant__ float cB[4];

#define ROWS_PER_BLOCK 1024   // 256 threads * 4 rows

__global__ __launch_bounds__(256, 6)
void lnsm_kernel(const float4* __restrict__ x4,
                 float4* __restrict__ out4)
{
    __shared__ float s[ROWS_PER_BLOCK * 3];   // 12 KB

    const int t = threadIdx.x;
    const size_t blockRow = (size_t)blockIdx.x * ROWS_PER_BLOCK;
    const float4* xb = x4 + blockRow;

    // Front-batch 4 coalesced loads for MLP.
    float4 v0 = xb[t];
    float4 v1 = xb[t + 256];
    float4 v2 = xb[t + 512];
    float4 v3 = xb[t + 768];

    float4 vs[4] = {v0, v1, v2, v3};

    #pragma unroll
    for (int r = 0; r < 4; r++) {
        float4 v = vs[r];
        float mu  = (v.x + v.y + v.z + v.w) * 0.25f;
        float a = v.x - mu, b = v.y - mu, c = v.z - mu, d = v.w - mu;
        float var = (a * a + b * b + c * c + d * d) * 0.25f;
        float inv = rsqrtf(var + 1e-5f);

        float h0 = a * inv * cG[0] + cB[0];
        float h1 = b * inv * cG[1] + cB[1];
        float h2 = c * inv * cG[2] + cB[2];
        float h3 = d * inv * cG[3] + cB[3];

        float l0 = h0 * cW[0] + h1 * cW[3] + h2 * cW[6] + h3 * cW[9];
        float l1 = h0 * cW[1] + h1 * cW[4] + h2 * cW[7] + h3 * cW[10];
        float l2 = h0 * cW[2] + h1 * cW[5] + h2 * cW[8] + h3 * cW[11];

        float m  = fmaxf(l0, fmaxf(l1, l2));
        float e0 = __expf(l0 - m);
        float e1 = __expf(l1 - m);
        float e2 = __expf(l2 - m);
        float rs = 1.0f / (e0 + e1 + e2);

        int row = t + 256 * r;
        s[row * 3 + 0] = e0 * rs;   // stride-3 float writes: 3 coprime 32 ->
        s[row * 3 + 1] = e1 * rs;   // bank-conflict-free
        s[row * 3 + 2] = e2 * rs;
    }

    __syncthreads();

    // Flush 768 float4 per block, perfectly coalesced.
    float4* ob = out4 + (size_t)blockIdx.x * (ROWS_PER_BLOCK * 3 / 4);
    const float4* s4 = (const float4*)s;
    ob[t]       = s4[t];
    ob[t + 256] = s4[t + 256];
    ob[t + 512] = s4[t + 512];
}

extern "C" void kernel_launch(void* const* d_in, const int* in_sizes, int n_in,
                              void* d_out, int out_size)
{
    const float* x     = (const float*)d_in[0];   // [N,4]
    const float* W     = (const float*)d_in[1];   // [4,3]
    const float* gamma = (const float*)d_in[2];   // [4]
    const float* beta  = (const float*)d_in[3];   // [4]
    float* out = (float*)d_out;                   // [N,3]

    // Graph-capturable D2D memcpy into constant bank.
    cudaMemcpyToSymbolAsync(cW, W,     12 * sizeof(float), 0, cudaMemcpyDeviceToDevice);
    cudaMemcpyToSymbolAsync(cG, gamma,  4 * sizeof(float), 0, cudaMemcpyDeviceToDevice);
    cudaMemcpyToSymbolAsync(cB, beta,   4 * sizeof(float), 0, cudaMemcpyDeviceToDevice);

    int n_rows = in_sizes[0] / 4;
    int blocks = n_rows / ROWS_PER_BLOCK;         // 8192, exact
    lnsm_kernel<<<blocks, 256>>>((const float4*)x, (float4*)out);
}

// round 4
// speedup vs baseline: 1.0568x; 1.0568x over previous
#include <cuda_runtime.h>

// LayerNormSoftmaxChain: x[N,4] -> LN(4) -> @W[4,3] -> softmax(3) -> out[N,3]
// N = 8388608. HBM-streaming: 16B in / 12B out per row (224 MiB total).
//
// R3: - no memcpy nodes in the graph (they cost ~12.7us wall in R2);
//       a 1-warp prep kernel folds gamma/beta into W on device:
//         A[i][j]   = gamma[i] * W[i][j]
//         colsum[j] = sum_i A[i][j]
//         c[j]      = sum_i beta[i] * W[i][j]
//       so per row: l_j = inv * (x . A_j - mu * colsum_j) + c_j
//     - __ldcs/__stcs streaming hints (working set >> L2)
//     - keeps R2's fully-coalesced loads + smem-staged coalesced stores

__device__ float gParams[18];   // A[12], colsum[3], c[3]

__global__ void lnsm_prep(const float* __restrict__ W,
                          const float* __restrict__ gamma,
                          const float* __restrict__ beta)
{
    if (threadIdx.x == 0 && blockIdx.x == 0) {
        float cs[3] = {0.f, 0.f, 0.f};
        float cc[3] = {0.f, 0.f, 0.f};
        #pragma unroll
        for (int i = 0; i < 4; i++) {
            float g = gamma[i], b = beta[i];
            #pragma unroll
            for (int j = 0; j < 3; j++) {
                float a = g * W[i * 3 + j];
                gParams[i * 3 + j] = a;
                cs[j] += a;
                cc[j] += b * W[i * 3 + j];
            }
        }
        #pragma unroll
        for (int j = 0; j < 3; j++) {
            gParams[12 + j] = cs[j];
            gParams[15 + j] = cc[j];
        }
    }
}

#define ROWS_PER_BLOCK 1024   // 256 threads * 4 rows

__global__ __launch_bounds__(256)
void lnsm_kernel(const float4* __restrict__ x4,
                 float4* __restrict__ out4)
{
    __shared__ float s[ROWS_PER_BLOCK * 3];   // 12 KB

    const int t = threadIdx.x;
    const float4* xb = x4 + (size_t)blockIdx.x * ROWS_PER_BLOCK;

    // Folded params (uniform broadcast loads, L1/L2-resident).
    float A0x = __ldg(gParams + 0),  A0y = __ldg(gParams + 1),  A0z = __ldg(gParams + 2);
    float A1x = __ldg(gParams + 3),  A1y = __ldg(gParams + 4),  A1z = __ldg(gParams + 5);
    float A2x = __ldg(gParams + 6),  A2y = __ldg(gParams + 7),  A2z = __ldg(gParams + 8);
    float A3x = __ldg(gParams + 9),  A3y = __ldg(gParams + 10), A3z = __ldg(gParams + 11);
    float csx = __ldg(gParams + 12), csy = __ldg(gParams + 13), csz = __ldg(gParams + 14);
    float ccx = __ldg(gParams + 15), ccy = __ldg(gParams + 16), ccz = __ldg(gParams + 17);

    // Front-batched coalesced streaming loads (evict-first).
    float4 vs[4];
    vs[0] = __ldcs(xb + t);
    vs[1] = __ldcs(xb + t + 256);
    vs[2] = __ldcs(xb + t + 512);
    vs[3] = __ldcs(xb + t + 768);

    #pragma unroll
    for (int r = 0; r < 4; r++) {
        float4 v = vs[r];
        float sum   = (v.x + v.y) + (v.z + v.w);
        float mu    = sum * 0.25f;
        float sumsq = fmaf(v.x, v.x, fmaf(v.y, v.y, fmaf(v.z, v.z, v.w * v.w)));
        float var   = fmaf(sumsq, 0.25f, -mu * mu);
        float inv   = rsqrtf(var + 1e-5f);

        float d0 = fmaf(v.x, A0x, fmaf(v.y, A1x, fmaf(v.z, A2x, v.w * A3x)));
        float d1 = fmaf(v.x, A0y, fmaf(v.y, A1y, fmaf(v.z, A2y, v.w * A3y)));
        float d2 = fmaf(v.x, A0z, fmaf(v.y, A1z, fmaf(v.z, A2z, v.w * A3z)));

        float l0 = fmaf(inv, fmaf(-mu, csx, d0), ccx);
        float l1 = fmaf(inv, fmaf(-mu, csy, d1), ccy);
        float l2 = fmaf(inv, fmaf(-mu, csz, d2), ccz);

        float m  = fmaxf(l0, fmaxf(l1, l2));
        float e0 = __expf(l0 - m);
        float e1 = __expf(l1 - m);
        float e2 = __expf(l2 - m);
        float rs = 1.0f / ((e0 + e1) + e2);

        int row = t + 256 * r;
        s[row * 3 + 0] = e0 * rs;   // stride-3: coprime with 32 banks, conflict-free
        s[row * 3 + 1] = e1 * rs;
        s[row * 3 + 2] = e2 * rs;
    }

    __syncthreads();

    // Flush 768 float4 per block, coalesced streaming stores.
    float4* ob = out4 + (size_t)blockIdx.x * (ROWS_PER_BLOCK * 3 / 4);
    const float4* s4 = (const float4*)s;
    __stcs(ob + t,       s4[t]);
    __stcs(ob + t + 256, s4[t + 256]);
    __stcs(ob + t + 512, s4[t + 512]);
}

extern "C" void kernel_launch(void* const* d_in, const int* in_sizes, int n_in,
                              void* d_out, int out_size)
{
    const float* x     = (const float*)d_in[0];   // [N,4]
    const float* W     = (const float*)d_in[1];   // [4,3]
    const float* gamma = (const float*)d_in[2];   // [4]
    const float* beta  = (const float*)d_in[3];   // [4]
    float* out = (float*)d_out;                   // [N,3]

    lnsm_prep<<<1, 32>>>(W, gamma, beta);

    int n_rows = in_sizes[0] / 4;
    int blocks = n_rows / ROWS_PER_BLOCK;         // 8192, exact
    lnsm_kernel<<<blocks, 256>>>((const float4*)x, (float4*)out);
}